// round 10
// baseline (speedup 1.0000x reference)
#include <cuda_runtime.h>
#include <cuda_fp16.h>
#include <cstdint>

#define T_   1024
#define H_   1024
#define E_   16
#define I_   512      // MOE_INTER
#define IS_  1024     // SHARED_INTER
#define GUW_ 2048     // 2*SHARED_INTER

// ---------------- scratch (device globals; no allocs) ----------------
__device__ int    g_counts[E_];
__device__ int    g_tok[E_ * T_];
__device__ float  g_wt[E_ * T_];
__device__ __half g_h[(size_t)E_ * T_ * I_];    // routed intermediate (fp16)
__device__ __half g_hs[(size_t)T_ * IS_];       // shared-expert intermediate
__device__ __half g_xh[(size_t)T_ * H_];        // x in fp16
__device__ __half g_wgT[(size_t)E_ * I_ * H_];  // w_gate^T  [E][I][H]
__device__ __half g_wuT[(size_t)E_ * I_ * H_];  // w_up^T    [E][I][H]
__device__ __half g_wdT[(size_t)E_ * H_ * I_];  // w_down^T  [E][H][I]
__device__ __half g_wguT[(size_t)GUW_ * H_];    // ws_gate_up^T [2Is][H]
__device__ __half g_wsdT[(size_t)H_ * IS_];     // ws_down^T    [H][Is]

// ---------------- helpers ----------------
__device__ __forceinline__ float silu_mul(float g, float u) {
    return (g / (1.f + __expf(-g))) * u;
}
__device__ __forceinline__ uint32_t smem_u32(const void* p) {
    uint32_t a;
    asm("{ .reg .u64 t; cvta.to.shared.u64 t, %1; cvt.u32.u64 %0, t; }" : "=r"(a) : "l"(p));
    return a;
}
// m16n8k16 fp16 MMA, fp32 accum
__device__ __forceinline__ void mma16(float* d, const uint32_t* a, const uint32_t* b) {
    asm volatile(
        "mma.sync.aligned.m16n8k16.row.col.f32.f16.f16.f32 "
        "{%0,%1,%2,%3}, {%4,%5,%6,%7}, {%8,%9}, {%0,%1,%2,%3};"
        : "+f"(d[0]), "+f"(d[1]), "+f"(d[2]), "+f"(d[3])
        : "r"(a[0]), "r"(a[1]), "r"(a[2]), "r"(a[3]), "r"(b[0]), "r"(b[1]));
}
#define CP16(dst, src) asm volatile("cp.async.ca.shared.global [%0], [%1], 16;" :: "r"(dst), "l"(src))
#define CP_COMMIT()    asm volatile("cp.async.commit_group;" ::: "memory")
#define CP_WAIT2()     asm volatile("cp.async.wait_group 2;" ::: "memory")

#define SAH      40                      // smem row stride (halves), conflict-free
#define A_H      (128 * SAH)             // A part of a stage (halves)
#define STAGE_H  (384 * SAH)             // A(128) + B(256) rows per stage
#define STAGE_B  (STAGE_H * 2)
#define NSTG     4
#define GEMM_SMEM (NSTG * STAGE_B + 1024)

// ---------------- pre-pass: conversions ----------------
__global__ void conv_x_kernel(const float* __restrict__ x) {
    int i = (blockIdx.x * 256 + threadIdx.x) * 4;
    float4 v = *(const float4*)(x + i);
    __half2 a = __floats2half2_rn(v.x, v.y), b = __floats2half2_rn(v.z, v.w);
    *(uint2*)(g_xh + i) = make_uint2(*(uint32_t*)&a, *(uint32_t*)&b);
}

// [R,C] fp32 row-major -> [C,R] fp16 row-major, per-matrix (blockIdx.z)
// 32x32 tile, float4 loads, uint2 (4-half) packed stores.
__global__ void transpose_f2h(const float* __restrict__ in, __half* __restrict__ out,
                              int R, int C) {
    __shared__ float tile[32][33];
    size_t mo = (size_t)blockIdx.z * R * C;
    in += mo; out += mo;
    int c0 = blockIdx.x * 32, r0 = blockIdx.y * 32;
    int tid = threadIdx.x;                  // 256 threads
    {
        int idx = tid * 4;                  // 1024 elems, 1 float4/thread
        int r = idx >> 5, c = idx & 31;
        float4 v = *(const float4*)(in + (size_t)(r0 + r) * C + c0 + c);
        tile[r][c] = v.x; tile[r][c + 1] = v.y; tile[r][c + 2] = v.z; tile[r][c + 3] = v.w;
    }
    __syncthreads();
    {
        int c = tid >> 3, rq = (tid & 7) * 4;    // out row c, 4 r's
        __half2 h0 = __floats2half2_rn(tile[rq][c],     tile[rq + 1][c]);
        __half2 h1 = __floats2half2_rn(tile[rq + 2][c], tile[rq + 3][c]);
        *(uint2*)(out + (size_t)(c0 + c) * R + r0 + rq) =
            make_uint2(*(uint32_t*)&h0, *(uint32_t*)&h1);
    }
}

// ---------------- router ----------------
__global__ void zero_counts_kernel() {
    if (threadIdx.x < E_) g_counts[threadIdx.x] = 0;
}

__global__ void router_kernel(const float* __restrict__ x,
                              const float* __restrict__ rw) {
    __shared__ float sx[H_];
    __shared__ float slog[E_];
    int t = blockIdx.x;
    for (int i = threadIdx.x; i < H_; i += blockDim.x) sx[i] = x[(size_t)t * H_ + i];
    __syncthreads();
    int e = threadIdx.x >> 4, lane = threadIdx.x & 15;
    float s = 0.f;
    const float* w = rw + (size_t)e * H_;
    for (int i = lane; i < H_; i += 16) s += sx[i] * w[i];
    #pragma unroll
    for (int off = 8; off; off >>= 1) s += __shfl_down_sync(0xffffffffu, s, off, 16);
    if (lane == 0) slog[e] = s;
    __syncthreads();
    if (threadIdx.x == 0) {
        float l[E_];
        #pragma unroll
        for (int i = 0; i < E_; i++) l[i] = slog[i];
        int idx[4]; float lv[4]; bool used[E_];
        #pragma unroll
        for (int i = 0; i < E_; i++) used[i] = false;
        for (int k = 0; k < 4; k++) {      // top-4 of logits == top-4 of probs
            int bi = -1; float bv = -1e30f;
            for (int i = 0; i < E_; i++)
                if (!used[i] && l[i] > bv) { bv = l[i]; bi = i; }
            used[bi] = true; idx[k] = bi; lv[k] = bv;
        }
        float m = lv[0], ws[4], sum = 0.f;  // softmax denom cancels under top-k norm
        for (int k = 0; k < 4; k++) { ws[k] = __expf(lv[k] - m); sum += ws[k]; }
        float inv = 1.f / sum;
        for (int k = 0; k < 4; k++) {
            int pos = atomicAdd(&g_counts[idx[k]], 1);
            g_tok[idx[k] * T_ + pos] = t;
            g_wt[idx[k] * T_ + pos]  = ws[k] * inv;
        }
    }
}

// =====================================================================
// GEMM1: h = silu(A Wg) * (A Wu)
// BM=128 tokens, BN=256 B-rows = 128 (g,u) pairs, BK=32
// 8 warps (2m x 4n), warp tile 64x64
// =====================================================================
__global__ __launch_bounds__(256)
void gemm1_mma() {
    extern __shared__ __half sh[];
    int z = blockIdx.z, cx = blockIdx.x, row0 = blockIdx.y * 128;
    int c0i = cx * 128;                    // output-column base (pairs)

    int cnt, e; const __half *bg, *bu; __half* hout; int ldo;
    if (z == 0) {
        e = -1; cnt = T_;
        bg = g_wguT + (size_t)c0i * H_;
        bu = g_wguT + (size_t)(IS_ + c0i) * H_;
        hout = g_hs + c0i; ldo = IS_;
    } else {
        e = z - 1;
        if (cx >= I_ / 128) return;
        cnt = g_counts[e];
        if (row0 >= cnt) return;
        bg = g_wgT + ((size_t)e * I_ + c0i) * H_;
        bu = g_wuT + ((size_t)e * I_ + c0i) * H_;
        hout = g_h + (size_t)e * T_ * I_ + c0i; ldo = I_;
    }
    if (row0 >= cnt) return;

    int* rows_s = (int*)(sh + NSTG * STAGE_H);
    int tid = threadIdx.x;
    if (tid < 128) {
        int r = row0 + tid;
        rows_s[tid] = (z == 0) ? r : ((r < cnt) ? g_tok[e * T_ + r] : -1);
    }
    __syncthreads();

    uint32_t smb = smem_u32(sh);
    // loaders: tid<128 -> A row tid (4 CP16); tid>=128 -> gu pair j (8 CP16)
    uint32_t dstA = 0, dstG = 0, dstU = 0;
    const __half *srcA = nullptr, *srcG = nullptr, *srcU = nullptr;
    if (tid < 128) {
        int tr = rows_s[tid];
        dstA = (uint32_t)tid * (SAH * 2);
        srcA = g_xh + (size_t)(tr < 0 ? 0 : tr) * H_;
    } else {
        int j = tid - 128;                 // pair 0..127 -> B rows 2j(g), 2j+1(u)
        dstG = (uint32_t)(A_H + (2 * j) * SAH) * 2;
        dstU = (uint32_t)(A_H + (2 * j + 1) * SAH) * 2;
        srcG = bg + (size_t)j * H_;
        srcU = bu + (size_t)j * H_;
    }

    int lane = tid & 31, wid = tid >> 5, gid = lane >> 2, t4 = lane & 3;
    int wm = wid & 1, wn = wid >> 1;       // 2 x 4 warp grid, 64x64 tiles
    float acc[4][8][4] = {};

    const int NIT = H_ / 32;
    #pragma unroll 1
    for (int p = 0; p < 3; p++) {
        uint32_t sb = smb + (uint32_t)p * STAGE_B;
        if (tid < 128) {
            uint32_t d = sb + dstA; const __half* s = srcA + p * 32;
            CP16(d, s); CP16(d + 16, s + 8); CP16(d + 32, s + 16); CP16(d + 48, s + 24);
        } else {
            uint32_t d = sb + dstG; const __half* s = srcG + p * 32;
            CP16(d, s); CP16(d + 16, s + 8); CP16(d + 32, s + 16); CP16(d + 48, s + 24);
            d = sb + dstU; s = srcU + p * 32;
            CP16(d, s); CP16(d + 16, s + 8); CP16(d + 32, s + 16); CP16(d + 48, s + 24);
        }
        CP_COMMIT();
    }
    for (int it = 0; it < NIT; ++it) {
        CP_WAIT2();
        __syncthreads();
        if (it + 3 < NIT) {
            uint32_t sb = smb + (uint32_t)((it + 3) & (NSTG - 1)) * STAGE_B;
            if (tid < 128) {
                uint32_t d = sb + dstA; const __half* s = srcA + (it + 3) * 32;
                CP16(d, s); CP16(d + 16, s + 8); CP16(d + 32, s + 16); CP16(d + 48, s + 24);
            } else {
                uint32_t d = sb + dstG; const __half* s = srcG + (it + 3) * 32;
                CP16(d, s); CP16(d + 16, s + 8); CP16(d + 32, s + 16); CP16(d + 48, s + 24);
                d = sb + dstU; s = srcU + (it + 3) * 32;
                CP16(d, s); CP16(d + 16, s + 8); CP16(d + 32, s + 16); CP16(d + 48, s + 24);
            }
            CP_COMMIT();
        }
        const __half* a = sh + (size_t)(it & (NSTG - 1)) * STAGE_H;
        const __half* b = a + A_H;
        #pragma unroll
        for (int kb = 0; kb < 32; kb += 16) {
            uint32_t af[4][4], bf[8][2];
            #pragma unroll
            for (int mi = 0; mi < 4; mi++) {
                int rm = wm * 64 + mi * 16 + gid;
                af[mi][0] = *(const uint32_t*)(a + rm * SAH + kb + 2 * t4);
                af[mi][1] = *(const uint32_t*)(a + (rm + 8) * SAH + kb + 2 * t4);
                af[mi][2] = *(const uint32_t*)(a + rm * SAH + kb + 8 + 2 * t4);
                af[mi][3] = *(const uint32_t*)(a + (rm + 8) * SAH + kb + 8 + 2 * t4);
            }
            #pragma unroll
            for (int ni = 0; ni < 8; ni++) {
                int n = wn * 64 + ni * 8 + gid;
                bf[ni][0] = *(const uint32_t*)(b + n * SAH + kb + 2 * t4);
                bf[ni][1] = *(const uint32_t*)(b + n * SAH + kb + 8 + 2 * t4);
            }
            #pragma unroll
            for (int mi = 0; mi < 4; mi++)
                #pragma unroll
                for (int ni = 0; ni < 8; ni++)
                    mma16(acc[mi][ni], af[mi], bf[ni]);
        }
        __syncthreads();
    }

    // epilogue: (d0,d1)=(g,u) of pair j = wn*32 + ni*4 + t4
    #pragma unroll
    for (int mi = 0; mi < 4; mi++) {
        #pragma unroll
        for (int ni = 0; ni < 8; ni++) {
            int rb = row0 + wm * 64 + mi * 16 + gid;
            int j  = wn * 32 + ni * 4 + t4;
            if (rb < cnt)
                hout[(size_t)rb * ldo + j] =
                    __float2half_rn(silu_mul(acc[mi][ni][0], acc[mi][ni][1]));
            if (rb + 8 < cnt)
                hout[(size_t)(rb + 8) * ldo + j] =
                    __float2half_rn(silu_mul(acc[mi][ni][2], acc[mi][ni][3]));
        }
    }
}

// =====================================================================
// GEMM2: out += w * (h Wdown)
// BM=128, BN=256, BK=32, 8 warps (2m x 4n), warp tile 64x64
// =====================================================================
__global__ __launch_bounds__(256)
void gemm2_mma(float* __restrict__ out) {
    extern __shared__ __half sh[];
    int z = blockIdx.z, col0 = blockIdx.x * 256, row0 = blockIdx.y * 128;

    int cnt, e, K; const __half *Ap, *Bp;
    if (z == 0) {
        e = -1; cnt = T_; K = IS_;
        Ap = g_hs;
        Bp = g_wsdT + (size_t)col0 * IS_;
    } else {
        e = z - 1; cnt = g_counts[e]; K = I_;
        if (row0 >= cnt) return;
        Ap = g_h + (size_t)e * T_ * I_;
        Bp = g_wdT + ((size_t)e * H_ + col0) * I_;
    }
    if (row0 >= cnt) return;

    uint32_t smb = smem_u32(sh);
    int tid = threadIdx.x;
    uint32_t dst0 = 0, dst1 = 0;
    const __half *src0 = nullptr, *src1 = nullptr;
    if (tid < 128) {
        int r = row0 + tid;
        if (r >= cnt) r = row0;            // clamp; result discarded
        dst0 = (uint32_t)tid * (SAH * 2);
        src0 = Ap + (size_t)r * K;
    } else {
        int m = tid - 128;                 // B rows 2m, 2m+1
        dst0 = (uint32_t)(A_H + (2 * m) * SAH) * 2;
        dst1 = (uint32_t)(A_H + (2 * m + 1) * SAH) * 2;
        src0 = Bp + (size_t)(2 * m) * K;
        src1 = Bp + (size_t)(2 * m + 1) * K;
    }

    int lane = tid & 31, wid = tid >> 5, gid = lane >> 2, t4 = lane & 3;
    int wm = wid & 1, wn = wid >> 1;
    float acc[4][8][4] = {};

    const int NIT = K / 32;
    #pragma unroll 1
    for (int p = 0; p < 3; p++) {
        uint32_t sb = smb + (uint32_t)p * STAGE_B;
        {
            uint32_t d = sb + dst0; const __half* s = src0 + p * 32;
            CP16(d, s); CP16(d + 16, s + 8); CP16(d + 32, s + 16); CP16(d + 48, s + 24);
        }
        if (tid >= 128) {
            uint32_t d = sb + dst1; const __half* s = src1 + p * 32;
            CP16(d, s); CP16(d + 16, s + 8); CP16(d + 32, s + 16); CP16(d + 48, s + 24);
        }
        CP_COMMIT();
    }
    for (int it = 0; it < NIT; ++it) {
        CP_WAIT2();
        __syncthreads();
        if (it + 3 < NIT) {
            uint32_t sb = smb + (uint32_t)((it + 3) & (NSTG - 1)) * STAGE_B;
            {
                uint32_t d = sb + dst0; const __half* s = src0 + (it + 3) * 32;
                CP16(d, s); CP16(d + 16, s + 8); CP16(d + 32, s + 16); CP16(d + 48, s + 24);
            }
            if (tid >= 128) {
                uint32_t d = sb + dst1; const __half* s = src1 + (it + 3) * 32;
                CP16(d, s); CP16(d + 16, s + 8); CP16(d + 32, s + 16); CP16(d + 48, s + 24);
            }
            CP_COMMIT();
        }
        const __half* a = sh + (size_t)(it & (NSTG - 1)) * STAGE_H;
        const __half* b = a + A_H;
        #pragma unroll
        for (int kb = 0; kb < 32; kb += 16) {
            uint32_t af[4][4], bf[8][2];
            #pragma unroll
            for (int mi = 0; mi < 4; mi++) {
                int rm = wm * 64 + mi * 16 + gid;
                af[mi][0] = *(const uint32_t*)(a + rm * SAH + kb + 2 * t4);
                af[mi][1] = *(const uint32_t*)(a + (rm + 8) * SAH + kb + 2 * t4);
                af[mi][2] = *(const uint32_t*)(a + rm * SAH + kb + 8 + 2 * t4);
                af[mi][3] = *(const uint32_t*)(a + (rm + 8) * SAH + kb + 8 + 2 * t4);
            }
            #pragma unroll
            for (int ni = 0; ni < 8; ni++) {
                int n = wn * 64 + ni * 8 + gid;
                bf[ni][0] = *(const uint32_t*)(b + n * SAH + kb + 2 * t4);
                bf[ni][1] = *(const uint32_t*)(b + n * SAH + kb + 8 + 2 * t4);
            }
            #pragma unroll
            for (int mi = 0; mi < 4; mi++)
                #pragma unroll
                for (int ni = 0; ni < 8; ni++)
                    mma16(acc[mi][ni], af[mi], bf[ni]);
        }
        __syncthreads();
    }

    // epilogue: weighted atomic accumulate
    #pragma unroll
    for (int mi = 0; mi < 4; mi++) {
        int rb = row0 + wm * 64 + mi * 16 + gid;
        #pragma unroll
        for (int h = 0; h < 2; h++) {
            int r = rb + h * 8;
            if (r < cnt) {
                int   t = (z == 0) ? r : g_tok[e * T_ + r];
                float w = (z == 0) ? 1.f : g_wt[e * T_ + r];
                float* op = out + (size_t)t * H_ + col0 + wn * 64;
                #pragma unroll
                for (int ni = 0; ni < 8; ni++) {
                    int c = ni * 8 + t4 * 2;
                    atomicAdd(op + c,     w * acc[mi][ni][h * 2 + 0]);
                    atomicAdd(op + c + 1, w * acc[mi][ni][h * 2 + 1]);
                }
            }
        }
    }
}

// ---------------- launch ----------------
extern "C" void kernel_launch(void* const* d_in, const int* in_sizes, int n_in,
                              void* d_out, int out_size) {
    const float* x   = (const float*)d_in[0];
    const float* rw  = (const float*)d_in[1];
    const float* wg  = (const float*)d_in[2];
    const float* wu  = (const float*)d_in[3];
    const float* wd  = (const float*)d_in[4];
    const float* wgu = (const float*)d_in[5];
    const float* wsd = (const float*)d_in[6];

    void *pwgT, *pwuT, *pwdT, *pwguT, *pwsdT;
    cudaGetSymbolAddress(&pwgT,  g_wgT);
    cudaGetSymbolAddress(&pwuT,  g_wuT);
    cudaGetSymbolAddress(&pwdT,  g_wdT);
    cudaGetSymbolAddress(&pwguT, g_wguT);
    cudaGetSymbolAddress(&pwsdT, g_wsdT);

    cudaFuncSetAttribute(gemm1_mma, cudaFuncAttributeMaxDynamicSharedMemorySize, GEMM_SMEM);
    cudaFuncSetAttribute(gemm2_mma, cudaFuncAttributeMaxDynamicSharedMemorySize, GEMM_SMEM);

    cudaMemsetAsync(d_out, 0, (size_t)out_size * sizeof(float), 0);
    zero_counts_kernel<<<1, 32>>>();
    router_kernel<<<T_, 256>>>(x, rw);

    conv_x_kernel<<<T_ * H_ / 1024, 256>>>(x);
    transpose_f2h<<<dim3(I_ / 32,  H_ / 32,  E_), 256>>>(wg,  (__half*)pwgT,  H_,  I_);
    transpose_f2h<<<dim3(I_ / 32,  H_ / 32,  E_), 256>>>(wu,  (__half*)pwuT,  H_,  I_);
    transpose_f2h<<<dim3(H_ / 32,  I_ / 32,  E_), 256>>>(wd,  (__half*)pwdT,  I_,  H_);
    transpose_f2h<<<dim3(GUW_ / 32, H_ / 32, 1),  256>>>(wgu, (__half*)pwguT, H_,  GUW_);
    transpose_f2h<<<dim3(H_ / 32,  IS_ / 32, 1),  256>>>(wsd, (__half*)pwsdT, IS_, H_);

    // z=0 = shared expert (largest K) scheduled first
    gemm1_mma<<<dim3(IS_ / 128, T_ / 128, E_ + 1), 256, GEMM_SMEM>>>();
    gemm2_mma<<<dim3(H_ / 256, T_ / 128, E_ + 1), 256, GEMM_SMEM>>>((float*)d_out);
}

// round 12
// speedup vs baseline: 1.1393x; 1.1393x over previous
#include <cuda_runtime.h>
#include <cuda_fp16.h>
#include <cstdint>

#define T_   1024
#define H_   1024
#define E_   16
#define I_   512      // MOE_INTER
#define IS_  1024     // SHARED_INTER
#define GUW_ 2048     // 2*SHARED_INTER

// ---------------- scratch (device globals; no allocs) ----------------
__device__ int    g_counts[E_];
__device__ int    g_tok[E_ * T_];
__device__ float  g_wt[E_ * T_];
__device__ __half g_h[(size_t)E_ * T_ * I_];    // routed intermediate (fp16)
__device__ __half g_hs[(size_t)T_ * IS_];       // shared-expert intermediate
__device__ __half g_xh[(size_t)T_ * H_];        // x in fp16
__device__ __half g_wgT[(size_t)E_ * I_ * H_];  // w_gate^T  [E][I][H]
__device__ __half g_wuT[(size_t)E_ * I_ * H_];  // w_up^T    [E][I][H]
__device__ __half g_wdT[(size_t)E_ * H_ * I_];  // w_down^T  [E][H][I]
__device__ __half g_wguT[(size_t)GUW_ * H_];    // ws_gate_up^T [2Is][H]
__device__ __half g_wsdT[(size_t)H_ * IS_];     // ws_down^T    [H][Is]

// ---------------- helpers ----------------
__device__ __forceinline__ float silu_mul(float g, float u) {
    return (g / (1.f + __expf(-g))) * u;
}
__device__ __forceinline__ uint32_t smem_u32(const void* p) {
    uint32_t a;
    asm("{ .reg .u64 t; cvta.to.shared.u64 t, %1; cvt.u32.u64 %0, t; }" : "=r"(a) : "l"(p));
    return a;
}
// m16n8k16 fp16 MMA, fp32 accum
__device__ __forceinline__ void mma16(float* d, const uint32_t* a, const uint32_t* b) {
    asm volatile(
        "mma.sync.aligned.m16n8k16.row.col.f32.f16.f16.f32 "
        "{%0,%1,%2,%3}, {%4,%5,%6,%7}, {%8,%9}, {%0,%1,%2,%3};"
        : "+f"(d[0]), "+f"(d[1]), "+f"(d[2]), "+f"(d[3])
        : "r"(a[0]), "r"(a[1]), "r"(a[2]), "r"(a[3]), "r"(b[0]), "r"(b[1]));
}
#define CP16(dst, src) asm volatile("cp.async.ca.shared.global [%0], [%1], 16;" :: "r"(dst), "l"(src))
#define CP_COMMIT()    asm volatile("cp.async.commit_group;" ::: "memory")
#define CP_WAIT2()     asm volatile("cp.async.wait_group 2;" ::: "memory")

#define SAH      40                      // smem row stride (halves), conflict-free
#define A_H      (128 * SAH)             // A part of a stage (halves)
#define STAGE_H  (256 * SAH)             // A+B stage (halves)
#define STAGE_B  (STAGE_H * 2)           // stage bytes
#define NSTG     4
#define GEMM_SMEM (NSTG * STAGE_B + 1024)

// ---------------- fused pre-pass: x->fp16 + 5 weight transposes ----------------
#define XBLKS     (T_ * H_ / 1024)                     // 1024
#define WG_TILES  ((I_ / 32) * (H_ / 32) * E_)         // 8192
#define WD_TILES  ((H_ / 32) * (I_ / 32) * E_)         // 8192
#define WGU_TILES ((GUW_ / 32) * (H_ / 32))            // 2048
#define WSD_TILES ((H_ / 32) * (IS_ / 32))             // 1024
#define PRE_BLKS  (XBLKS + 2 * WG_TILES + WD_TILES + WGU_TILES + WSD_TILES)  // 28672

__global__ void prepass_kernel(const float* __restrict__ x,
                               const float* __restrict__ wg,
                               const float* __restrict__ wu,
                               const float* __restrict__ wd,
                               const float* __restrict__ wgu,
                               const float* __restrict__ wsd) {
    __shared__ float tb[32][33];
    int b = blockIdx.x, tid = threadIdx.x;
    if (b < XBLKS) {                                   // x -> fp16 (no transpose)
        int i = (b * 256 + tid) * 4;
        float4 v = *(const float4*)(x + i);
        __half2 a = __floats2half2_rn(v.x, v.y), c = __floats2half2_rn(v.z, v.w);
        *(uint2*)(g_xh + i) = make_uint2(*(uint32_t*)&a, *(uint32_t*)&c);
        return;
    }
    b -= XBLKS;
    const float* in; __half* out; int R, C, tile;
    if (b < WG_TILES)                { in = wg;  out = g_wgT;  R = H_;  C = I_;   tile = b; }
    else if (b < 2 * WG_TILES)       { in = wu;  out = g_wuT;  R = H_;  C = I_;   tile = b - WG_TILES; }
    else if (b < 2 * WG_TILES + WD_TILES)
                                     { in = wd;  out = g_wdT;  R = I_;  C = H_;   tile = b - 2 * WG_TILES; }
    else if (b < 2 * WG_TILES + WD_TILES + WGU_TILES)
                                     { in = wgu; out = g_wguT; R = H_;  C = GUW_; tile = b - 2 * WG_TILES - WD_TILES; }
    else                             { in = wsd; out = g_wsdT; R = IS_; C = H_;   tile = b - 2 * WG_TILES - WD_TILES - WGU_TILES; }

    int ct32 = C >> 5, rt32 = R >> 5, per = ct32 * rt32;
    int mz = tile / per, t2 = tile % per;
    int c0 = (t2 % ct32) * 32, r0 = (t2 / ct32) * 32;
    size_t mo = (size_t)mz * R * C;
    in += mo; out += mo;

    {   // load 32x32 fp32 tile (1 float4 per thread)
        int idx = tid * 4, r = idx >> 5, c = idx & 31;
        float4 v = *(const float4*)(in + (size_t)(r0 + r) * C + c0 + c);
        tb[r][c] = v.x; tb[r][c + 1] = v.y; tb[r][c + 2] = v.z; tb[r][c + 3] = v.w;
    }
    __syncthreads();
    {   // store transposed as fp16 (4 halves = 8B per thread)
        int c = tid >> 3, rq = (tid & 7) * 4;
        __half2 h0 = __floats2half2_rn(tb[rq][c],     tb[rq + 1][c]);
        __half2 h1 = __floats2half2_rn(tb[rq + 2][c], tb[rq + 3][c]);
        *(uint2*)(out + (size_t)(c0 + c) * R + r0 + rq) =
            make_uint2(*(uint32_t*)&h0, *(uint32_t*)&h1);
    }
}

// ---------------- router ----------------
__global__ void zero_counts_kernel() {
    if (threadIdx.x < E_) g_counts[threadIdx.x] = 0;
}

__global__ void router_kernel(const float* __restrict__ x,
                              const float* __restrict__ rw) {
    __shared__ float sx[H_];
    __shared__ float slog[E_];
    int t = blockIdx.x;
    for (int i = threadIdx.x; i < H_; i += blockDim.x) sx[i] = x[(size_t)t * H_ + i];
    __syncthreads();
    int e = threadIdx.x >> 4, lane = threadIdx.x & 15;
    float s = 0.f;
    const float* w = rw + (size_t)e * H_;
    for (int i = lane; i < H_; i += 16) s += sx[i] * w[i];
    #pragma unroll
    for (int off = 8; off; off >>= 1) s += __shfl_down_sync(0xffffffffu, s, off, 16);
    if (lane == 0) slog[e] = s;
    __syncthreads();
    if (threadIdx.x == 0) {
        float l[E_];
        #pragma unroll
        for (int i = 0; i < E_; i++) l[i] = slog[i];
        int idx[4]; float lv[4]; bool used[E_];
        #pragma unroll
        for (int i = 0; i < E_; i++) used[i] = false;
        for (int k = 0; k < 4; k++) {      // top-4 of logits == top-4 of probs
            int bi = -1; float bv = -1e30f;
            for (int i = 0; i < E_; i++)
                if (!used[i] && l[i] > bv) { bv = l[i]; bi = i; }
            used[bi] = true; idx[k] = bi; lv[k] = bv;
        }
        float m = lv[0], ws[4], sum = 0.f;  // softmax denom cancels under top-k norm
        for (int k = 0; k < 4; k++) { ws[k] = __expf(lv[k] - m); sum += ws[k]; }
        float inv = 1.f / sum;
        for (int k = 0; k < 4; k++) {
            int pos = atomicAdd(&g_counts[idx[k]], 1);
            g_tok[idx[k] * T_ + pos] = t;
            g_wt[idx[k] * T_ + pos]  = ws[k] * inv;
        }
    }
}

// =====================================================================
// GEMM1: h = silu(A Wg) * (A Wu); all-fp16 cp.async pipeline
// BM=128 tokens, 128 B-rows = 64 (g,u) interleaved pairs, BK=32, 8 warps
// =====================================================================
__global__ __launch_bounds__(256, 2)
void gemm1_mma() {
    extern __shared__ __half sh[];
    int z = blockIdx.z, cx = blockIdx.x, row0 = blockIdx.y * 128;
    int c0i = cx * 64;

    int cnt, e; const __half *bg, *bu; __half* hout; int ldo;
    if (z == 0) {
        e = -1; cnt = T_;
        bg = g_wguT + (size_t)c0i * H_;
        bu = g_wguT + (size_t)(IS_ + c0i) * H_;
        hout = g_hs + c0i; ldo = IS_;
    } else {
        e = z - 1;
        if (cx >= I_ / 64) return;
        cnt = g_counts[e];
        if (row0 >= cnt) return;
        bg = g_wgT + ((size_t)e * I_ + c0i) * H_;
        bu = g_wuT + ((size_t)e * I_ + c0i) * H_;
        hout = g_h + (size_t)e * T_ * I_ + c0i; ldo = I_;
    }
    if (row0 >= cnt) return;

    int* rows_s = (int*)(sh + NSTG * STAGE_H);
    int tid = threadIdx.x;
    if (tid < 128) {
        int r = row0 + tid;
        rows_s[tid] = (z == 0) ? r : ((r < cnt) ? g_tok[e * T_ + r] : -1);
    }
    __syncthreads();

    uint32_t smb = smem_u32(sh);
    // loader role: tid<128 -> A row tid; tid>=128 -> B row tid-128
    uint32_t dst_off;
    const __half* src;
    if (tid < 128) {
        int tr = rows_s[tid];
        dst_off = (uint32_t)tid * (SAH * 2);
        src = g_xh + (size_t)(tr < 0 ? 0 : tr) * H_;
    } else {
        int n = tid - 128, j = n >> 1;
        dst_off = (uint32_t)(A_H + n * SAH) * 2;
        src = ((n & 1) ? bu : bg) + (size_t)j * H_;
    }

    int lane = tid & 31, wid = tid >> 5, gid = lane >> 2, t4 = lane & 3;
    int wm = wid & 3, wn = wid >> 2;
    float acc[2][8][4] = {};

    const int NIT = H_ / 32;
    #pragma unroll 1
    for (int p = 0; p < 3; p++) {
        uint32_t d = smb + (uint32_t)p * STAGE_B + dst_off;
        const __half* s = src + p * 32;
        CP16(d, s); CP16(d + 16, s + 8); CP16(d + 32, s + 16); CP16(d + 48, s + 24);
        CP_COMMIT();
    }
    for (int it = 0; it < NIT; ++it) {
        CP_WAIT2();
        __syncthreads();
        if (it + 3 < NIT) {
            int st = (it + 3) & (NSTG - 1);
            uint32_t d = smb + (uint32_t)st * STAGE_B + dst_off;
            const __half* s = src + (it + 3) * 32;
            CP16(d, s); CP16(d + 16, s + 8); CP16(d + 32, s + 16); CP16(d + 48, s + 24);
            CP_COMMIT();
        }
        const __half* a = sh + (size_t)(it & (NSTG - 1)) * STAGE_H;
        const __half* b = a + A_H;
        #pragma unroll
        for (int kb = 0; kb < 32; kb += 16) {
            uint32_t af[2][4], bf[8][2];
            #pragma unroll
            for (int mi = 0; mi < 2; mi++) {
                int rm = wm * 32 + mi * 16 + gid;
                af[mi][0] = *(const uint32_t*)(a + rm * SAH + kb + 2 * t4);
                af[mi][1] = *(const uint32_t*)(a + (rm + 8) * SAH + kb + 2 * t4);
                af[mi][2] = *(const uint32_t*)(a + rm * SAH + kb + 8 + 2 * t4);
                af[mi][3] = *(const uint32_t*)(a + (rm + 8) * SAH + kb + 8 + 2 * t4);
            }
            #pragma unroll
            for (int ni = 0; ni < 8; ni++) {
                int n = wn * 64 + ni * 8 + gid;
                bf[ni][0] = *(const uint32_t*)(b + n * SAH + kb + 2 * t4);
                bf[ni][1] = *(const uint32_t*)(b + n * SAH + kb + 8 + 2 * t4);
            }
            #pragma unroll
            for (int mi = 0; mi < 2; mi++)
                #pragma unroll
                for (int ni = 0; ni < 8; ni++)
                    mma16(acc[mi][ni], af[mi], bf[ni]);
        }
        __syncthreads();
    }

    // epilogue: (d0,d1)=(g,u) pair for col j = wn*32 + ni*4 + t4
    #pragma unroll
    for (int mi = 0; mi < 2; mi++) {
        #pragma unroll
        for (int ni = 0; ni < 8; ni++) {
            int rb = row0 + wm * 32 + mi * 16 + gid;
            int j  = wn * 32 + ni * 4 + t4;
            if (rb < cnt)
                hout[(size_t)rb * ldo + j] =
                    __float2half_rn(silu_mul(acc[mi][ni][0], acc[mi][ni][1]));
            if (rb + 8 < cnt)
                hout[(size_t)(rb + 8) * ldo + j] =
                    __float2half_rn(silu_mul(acc[mi][ni][2], acc[mi][ni][3]));
        }
    }
}

// =====================================================================
// GEMM2: out += w * (h Wdown); all-fp16 cp.async pipeline
// BM=128, BN=128, BK=32, 8 warps, warp tile 32x64
// =====================================================================
__global__ __launch_bounds__(256, 2)
void gemm2_mma(float* __restrict__ out) {
    extern __shared__ __half sh[];
    int z = blockIdx.z, col0 = blockIdx.x * 128, row0 = blockIdx.y * 128;

    int cnt, e, K; const __half *Ap, *Bp;
    if (z == 0) {
        e = -1; cnt = T_; K = IS_;
        Ap = g_hs;
        Bp = g_wsdT + (size_t)col0 * IS_;
    } else {
        e = z - 1; cnt = g_counts[e]; K = I_;
        if (row0 >= cnt) return;
        Ap = g_h + (size_t)e * T_ * I_;
        Bp = g_wdT + ((size_t)e * H_ + col0) * I_;
    }
    if (row0 >= cnt) return;

    uint32_t smb = smem_u32(sh);
    int tid = threadIdx.x;
    uint32_t dst_off;
    const __half* src;
    if (tid < 128) {
        int r = row0 + tid;
        if (r >= cnt) r = row0;          // clamp; result discarded
        dst_off = (uint32_t)tid * (SAH * 2);
        src = Ap + (size_t)r * K;
    } else {
        int n = tid - 128;
        dst_off = (uint32_t)(A_H + n * SAH) * 2;
        src = Bp + (size_t)n * K;
    }

    int lane = tid & 31, wid = tid >> 5, gid = lane >> 2, t4 = lane & 3;
    int wm = wid & 3, wn = wid >> 2;
    float acc[2][8][4] = {};

    const int NIT = K / 32;
    #pragma unroll 1
    for (int p = 0; p < 3; p++) {
        uint32_t d = smb + (uint32_t)p * STAGE_B + dst_off;
        const __half* s = src + p * 32;
        CP16(d, s); CP16(d + 16, s + 8); CP16(d + 32, s + 16); CP16(d + 48, s + 24);
        CP_COMMIT();
    }
    for (int it = 0; it < NIT; ++it) {
        CP_WAIT2();
        __syncthreads();
        if (it + 3 < NIT) {
            int st = (it + 3) & (NSTG - 1);
            uint32_t d = smb + (uint32_t)st * STAGE_B + dst_off;
            const __half* s = src + (it + 3) * 32;
            CP16(d, s); CP16(d + 16, s + 8); CP16(d + 32, s + 16); CP16(d + 48, s + 24);
            CP_COMMIT();
        }
        const __half* a = sh + (size_t)(it & (NSTG - 1)) * STAGE_H;
        const __half* b = a + A_H;
        #pragma unroll
        for (int kb = 0; kb < 32; kb += 16) {
            uint32_t af[2][4], bf[8][2];
            #pragma unroll
            for (int mi = 0; mi < 2; mi++) {
                int rm = wm * 32 + mi * 16 + gid;
                af[mi][0] = *(const uint32_t*)(a + rm * SAH + kb + 2 * t4);
                af[mi][1] = *(const uint32_t*)(a + (rm + 8) * SAH + kb + 2 * t4);
                af[mi][2] = *(const uint32_t*)(a + rm * SAH + kb + 8 + 2 * t4);
                af[mi][3] = *(const uint32_t*)(a + (rm + 8) * SAH + kb + 8 + 2 * t4);
            }
            #pragma unroll
            for (int ni = 0; ni < 8; ni++) {
                int n = wn * 64 + ni * 8 + gid;
                bf[ni][0] = *(const uint32_t*)(b + n * SAH + kb + 2 * t4);
                bf[ni][1] = *(const uint32_t*)(b + n * SAH + kb + 8 + 2 * t4);
            }
            #pragma unroll
            for (int mi = 0; mi < 2; mi++)
                #pragma unroll
                for (int ni = 0; ni < 8; ni++)
                    mma16(acc[mi][ni], af[mi], bf[ni]);
        }
        __syncthreads();
    }

    // epilogue: weighted atomic accumulate
    #pragma unroll
    for (int mi = 0; mi < 2; mi++) {
        int rb = row0 + wm * 32 + mi * 16 + gid;
        #pragma unroll
        for (int h = 0; h < 2; h++) {
            int r = rb + h * 8;
            if (r < cnt) {
                int   t = (z == 0) ? r : g_tok[e * T_ + r];
                float w = (z == 0) ? 1.f : g_wt[e * T_ + r];
                float* op = out + (size_t)t * H_ + col0 + wn * 64;
                #pragma unroll
                for (int ni = 0; ni < 8; ni++) {
                    int c = ni * 8 + t4 * 2;
                    atomicAdd(op + c,     w * acc[mi][ni][h * 2 + 0]);
                    atomicAdd(op + c + 1, w * acc[mi][ni][h * 2 + 1]);
                }
            }
        }
    }
}

// ---------------- launch ----------------
extern "C" void kernel_launch(void* const* d_in, const int* in_sizes, int n_in,
                              void* d_out, int out_size) {
    const float* x   = (const float*)d_in[0];
    const float* rw  = (const float*)d_in[1];
    const float* wg  = (const float*)d_in[2];
    const float* wu  = (const float*)d_in[3];
    const float* wd  = (const float*)d_in[4];
    const float* wgu = (const float*)d_in[5];
    const float* wsd = (const float*)d_in[6];

    cudaFuncSetAttribute(gemm1_mma, cudaFuncAttributeMaxDynamicSharedMemorySize, GEMM_SMEM);
    cudaFuncSetAttribute(gemm2_mma, cudaFuncAttributeMaxDynamicSharedMemorySize, GEMM_SMEM);

    cudaMemsetAsync(d_out, 0, (size_t)out_size * sizeof(float), 0);
    zero_counts_kernel<<<1, 32>>>();
    router_kernel<<<T_, 256>>>(x, rw);
    prepass_kernel<<<PRE_BLKS, 256>>>(x, wg, wu, wd, wgu, wsd);

    // z=0 = shared expert (largest K) scheduled first
    gemm1_mma<<<dim3(IS_ / 64, T_ / 128, E_ + 1), 256, GEMM_SMEM>>>();
    gemm2_mma<<<dim3(H_ / 128, T_ / 128, E_ + 1), 256, GEMM_SMEM>>>((float*)d_out);
}

// round 14
// speedup vs baseline: 1.1611x; 1.0192x over previous
#include <cuda_runtime.h>
#include <cuda_fp16.h>
#include <cstdint>

#define T_   1024
#define H_   1024
#define E_   16
#define I_   512      // MOE_INTER
#define IS_  1024     // SHARED_INTER
#define GUW_ 2048     // 2*SHARED_INTER

// ---------------- scratch (device globals; no allocs) ----------------
__device__ int    g_counts[E_];
__device__ int    g_tok[E_ * T_];
__device__ float  g_wt[E_ * T_];
__device__ __half g_h[(size_t)E_ * T_ * I_];    // routed intermediate (fp16)
__device__ __half g_hs[(size_t)T_ * IS_];       // shared-expert intermediate
__device__ __half g_xh[(size_t)T_ * H_];        // x in fp16
__device__ __half g_wgT[(size_t)E_ * I_ * H_];  // w_gate^T  [E][I][H]
__device__ __half g_wuT[(size_t)E_ * I_ * H_];  // w_up^T    [E][I][H]
__device__ __half g_wdT[(size_t)E_ * H_ * I_];  // w_down^T  [E][H][I]
__device__ __half g_wguT[(size_t)GUW_ * H_];    // ws_gate_up^T [2Is][H]
__device__ __half g_wsdT[(size_t)H_ * IS_];     // ws_down^T    [H][Is]

// ---------------- helpers ----------------
__device__ __forceinline__ float silu_mul(float g, float u) {
    return (g / (1.f + __expf(-g))) * u;
}
__device__ __forceinline__ uint32_t smem_u32(const void* p) {
    uint32_t a;
    asm("{ .reg .u64 t; cvta.to.shared.u64 t, %1; cvt.u32.u64 %0, t; }" : "=r"(a) : "l"(p));
    return a;
}
// m16n8k16 fp16 MMA, fp32 accum
__device__ __forceinline__ void mma16(float* d, const uint32_t* a, const uint32_t* b) {
    asm volatile(
        "mma.sync.aligned.m16n8k16.row.col.f32.f16.f16.f32 "
        "{%0,%1,%2,%3}, {%4,%5,%6,%7}, {%8,%9}, {%0,%1,%2,%3};"
        : "+f"(d[0]), "+f"(d[1]), "+f"(d[2]), "+f"(d[3])
        : "r"(a[0]), "r"(a[1]), "r"(a[2]), "r"(a[3]), "r"(b[0]), "r"(b[1]));
}
#define CP16(dst, src) asm volatile("cp.async.cg.shared.global [%0], [%1], 16;" :: "r"(dst), "l"(src))
#define CP_COMMIT()    asm volatile("cp.async.commit_group;" ::: "memory")
#define CP_WAIT(n)     asm volatile("cp.async.wait_group %0;" :: "n"(n) : "memory")
#define LDSM4(R0, R1, R2, R3, ADDR)                                          \
    asm volatile("ldmatrix.sync.aligned.m8n8.x4.shared.b16 {%0,%1,%2,%3}, [%4];" \
        : "=r"(R0), "=r"(R1), "=r"(R2), "=r"(R3) : "r"(ADDR))

#define SAH      40                      // smem row stride (halves): 80B, conflict-free
#define A_H      (128 * SAH)             // A part of a stage (halves)
#define STAGE_H  (256 * SAH)             // A+B stage (halves)
#define STAGE_B  (STAGE_H * 2)           // stage bytes
#define NSTG     4
#define GEMM_SMEM (NSTG * STAGE_B + 1024)

// ---------------- fused pre-pass: x->fp16 + 5 weight transposes ----------------
#define XBLKS     (T_ * H_ / 1024)                     // 1024
#define WG_TILES  ((I_ / 32) * (H_ / 32) * E_)         // 8192
#define WD_TILES  ((H_ / 32) * (I_ / 32) * E_)         // 8192
#define WGU_TILES ((GUW_ / 32) * (H_ / 32))            // 2048
#define WSD_TILES ((H_ / 32) * (IS_ / 32))             // 1024
#define PRE_BLKS  (XBLKS + 2 * WG_TILES + WD_TILES + WGU_TILES + WSD_TILES)  // 28672

__global__ void prepass_kernel(const float* __restrict__ x,
                               const float* __restrict__ wg,
                               const float* __restrict__ wu,
                               const float* __restrict__ wd,
                               const float* __restrict__ wgu,
                               const float* __restrict__ wsd) {
    __shared__ float tb[32][33];
    int b = blockIdx.x, tid = threadIdx.x;
    if (b < XBLKS) {                                   // x -> fp16 (no transpose)
        int i = (b * 256 + tid) * 4;
        float4 v = *(const float4*)(x + i);
        __half2 a = __floats2half2_rn(v.x, v.y), c = __floats2half2_rn(v.z, v.w);
        *(uint2*)(g_xh + i) = make_uint2(*(uint32_t*)&a, *(uint32_t*)&c);
        return;
    }
    b -= XBLKS;
    const float* in; __half* out; int R, C, tile;
    if (b < WG_TILES)                { in = wg;  out = g_wgT;  R = H_;  C = I_;   tile = b; }
    else if (b < 2 * WG_TILES)       { in = wu;  out = g_wuT;  R = H_;  C = I_;   tile = b - WG_TILES; }
    else if (b < 2 * WG_TILES + WD_TILES)
                                     { in = wd;  out = g_wdT;  R = I_;  C = H_;   tile = b - 2 * WG_TILES; }
    else if (b < 2 * WG_TILES + WD_TILES + WGU_TILES)
                                     { in = wgu; out = g_wguT; R = H_;  C = GUW_; tile = b - 2 * WG_TILES - WD_TILES; }
    else                             { in = wsd; out = g_wsdT; R = IS_; C = H_;   tile = b - 2 * WG_TILES - WD_TILES - WGU_TILES; }

    int ct32 = C >> 5, rt32 = R >> 5, per = ct32 * rt32;
    int mz = tile / per, t2 = tile % per;
    int c0 = (t2 % ct32) * 32, r0 = (t2 / ct32) * 32;
    size_t mo = (size_t)mz * R * C;
    in += mo; out += mo;

    {   // load 32x32 fp32 tile (1 float4 per thread)
        int idx = tid * 4, r = idx >> 5, c = idx & 31;
        float4 v = *(const float4*)(in + (size_t)(r0 + r) * C + c0 + c);
        tb[r][c] = v.x; tb[r][c + 1] = v.y; tb[r][c + 2] = v.z; tb[r][c + 3] = v.w;
    }
    __syncthreads();
    {   // store transposed as fp16 (4 halves = 8B per thread)
        int c = tid >> 3, rq = (tid & 7) * 4;
        __half2 h0 = __floats2half2_rn(tb[rq][c],     tb[rq + 1][c]);
        __half2 h1 = __floats2half2_rn(tb[rq + 2][c], tb[rq + 3][c]);
        *(uint2*)(out + (size_t)(c0 + c) * R + r0 + rq) =
            make_uint2(*(uint32_t*)&h0, *(uint32_t*)&h1);
    }
}

// ---------------- router ----------------
__global__ void zero_counts_kernel() {
    if (threadIdx.x < E_) g_counts[threadIdx.x] = 0;
}

__global__ void router_kernel(const float* __restrict__ x,
                              const float* __restrict__ rw) {
    __shared__ float sx[H_];
    __shared__ float slog[E_];
    int t = blockIdx.x;
    for (int i = threadIdx.x; i < H_; i += blockDim.x) sx[i] = x[(size_t)t * H_ + i];
    __syncthreads();
    int e = threadIdx.x >> 4, lane = threadIdx.x & 15;
    float s = 0.f;
    const float* w = rw + (size_t)e * H_;
    for (int i = lane; i < H_; i += 16) s += sx[i] * w[i];
    #pragma unroll
    for (int off = 8; off; off >>= 1) s += __shfl_down_sync(0xffffffffu, s, off, 16);
    if (lane == 0) slog[e] = s;
    __syncthreads();
    if (threadIdx.x == 0) {
        float l[E_];
        #pragma unroll
        for (int i = 0; i < E_; i++) l[i] = slog[i];
        int idx[4]; float lv[4]; bool used[E_];
        #pragma unroll
        for (int i = 0; i < E_; i++) used[i] = false;
        for (int k = 0; k < 4; k++) {      // top-4 of logits == top-4 of probs
            int bi = -1; float bv = -1e30f;
            for (int i = 0; i < E_; i++)
                if (!used[i] && l[i] > bv) { bv = l[i]; bi = i; }
            used[bi] = true; idx[k] = bi; lv[k] = bv;
        }
        float m = lv[0], ws[4], sum = 0.f;  // softmax denom cancels under top-k norm
        for (int k = 0; k < 4; k++) { ws[k] = __expf(lv[k] - m); sum += ws[k]; }
        float inv = 1.f / sum;
        for (int k = 0; k < 4; k++) {
            int pos = atomicAdd(&g_counts[idx[k]], 1);
            g_tok[idx[k] * T_ + pos] = t;
            g_wt[idx[k] * T_ + pos]  = ws[k] * inv;
        }
    }
}

// =====================================================================
// GEMM1: h = silu(A Wg) * (A Wu); fp16 cp.async + ldmatrix pipeline
// BM=128 tokens, 128 B-rows = 64 (g,u) interleaved pairs, BK=32, 8 warps
// =====================================================================
__global__ __launch_bounds__(256, 2)
void gemm1_mma() {
    extern __shared__ __half sh[];
    int z = blockIdx.z, cx = blockIdx.x, row0 = blockIdx.y * 128;
    int c0i = cx * 64;

    int cnt, e; const __half *bg, *bu; __half* hout; int ldo;
    if (z == 0) {
        e = -1; cnt = T_;
        bg = g_wguT + (size_t)c0i * H_;
        bu = g_wguT + (size_t)(IS_ + c0i) * H_;
        hout = g_hs + c0i; ldo = IS_;
    } else {
        e = z - 1;
        if (cx >= I_ / 64) return;
        cnt = g_counts[e];
        if (row0 >= cnt) return;
        bg = g_wgT + ((size_t)e * I_ + c0i) * H_;
        bu = g_wuT + ((size_t)e * I_ + c0i) * H_;
        hout = g_h + (size_t)e * T_ * I_ + c0i; ldo = I_;
    }
    if (row0 >= cnt) return;

    int* rows_s = (int*)(sh + NSTG * STAGE_H);
    int tid = threadIdx.x;
    if (tid < 128) {
        int r = row0 + tid;
        rows_s[tid] = (z == 0) ? r : ((r < cnt) ? g_tok[e * T_ + r] : -1);
    }
    __syncthreads();

    uint32_t smb = smem_u32(sh);
    // loader role: tid<128 -> A row tid; tid>=128 -> B row tid-128
    uint32_t dst_off;
    const __half* src;
    if (tid < 128) {
        int tr = rows_s[tid];
        dst_off = (uint32_t)tid * (SAH * 2);
        src = g_xh + (size_t)(tr < 0 ? 0 : tr) * H_;
    } else {
        int n = tid - 128, j = n >> 1;
        dst_off = (uint32_t)(A_H + n * SAH) * 2;
        src = ((n & 1) ? bu : bg) + (size_t)j * H_;
    }

    int lane = tid & 31, wid = tid >> 5, gid = lane >> 2, t4 = lane & 3;
    int wm = wid & 3, wn = wid >> 2;

    // ldmatrix per-lane byte offsets (within a stage)
    uint32_t aOff = ((uint32_t)(wm * 32 + (lane & 15)) * SAH + (uint32_t)(lane >> 4) * 8) * 2;
    uint32_t bOff = ((uint32_t)A_H +
                     (uint32_t)(wn * 64 + (lane & 7) + ((lane >> 4) & 1) * 8) * SAH +
                     (uint32_t)((lane >> 3) & 1) * 8) * 2;

    float acc[2][8][4] = {};

    const int NIT = H_ / 32;
    #pragma unroll 1
    for (int p = 0; p < 3; p++) {
        uint32_t d = smb + (uint32_t)p * STAGE_B + dst_off;
        const __half* s = src + p * 32;
        CP16(d, s); CP16(d + 16, s + 8); CP16(d + 32, s + 16); CP16(d + 48, s + 24);
        CP_COMMIT();
    }
    for (int it = 0; it < NIT; ++it) {
        if (it < NIT - 3) CP_WAIT(2); else CP_WAIT(0);
        __syncthreads();
        if (it + 3 < NIT) {
            uint32_t d = smb + (uint32_t)((it + 3) & (NSTG - 1)) * STAGE_B + dst_off;
            const __half* s = src + (it + 3) * 32;
            CP16(d, s); CP16(d + 16, s + 8); CP16(d + 32, s + 16); CP16(d + 48, s + 24);
            CP_COMMIT();
        }
        uint32_t sbase = smb + (uint32_t)(it & (NSTG - 1)) * STAGE_B;
        #pragma unroll
        for (int kb = 0; kb < 32; kb += 16) {
            uint32_t af[2][4], bf[8][2];
            #pragma unroll
            for (int mi = 0; mi < 2; mi++)
                LDSM4(af[mi][0], af[mi][1], af[mi][2], af[mi][3],
                      sbase + aOff + (uint32_t)(mi * 16 * SAH + kb) * 2);
            #pragma unroll
            for (int nj = 0; nj < 4; nj++)
                LDSM4(bf[2 * nj][0], bf[2 * nj][1], bf[2 * nj + 1][0], bf[2 * nj + 1][1],
                      sbase + bOff + (uint32_t)(nj * 16 * SAH + kb) * 2);
            #pragma unroll
            for (int mi = 0; mi < 2; mi++)
                #pragma unroll
                for (int ni = 0; ni < 8; ni++)
                    mma16(acc[mi][ni], af[mi], bf[ni]);
        }
        // no trailing sync: next iteration's top sync orders reuse
    }

    // epilogue: (d0,d1)=(g,u) pair for col j = wn*32 + ni*4 + t4
    #pragma unroll
    for (int mi = 0; mi < 2; mi++) {
        #pragma unroll
        for (int ni = 0; ni < 8; ni++) {
            int rb = row0 + wm * 32 + mi * 16 + gid;
            int j  = wn * 32 + ni * 4 + t4;
            if (rb < cnt)
                hout[(size_t)rb * ldo + j] =
                    __float2half_rn(silu_mul(acc[mi][ni][0], acc[mi][ni][1]));
            if (rb + 8 < cnt)
                hout[(size_t)(rb + 8) * ldo + j] =
                    __float2half_rn(silu_mul(acc[mi][ni][2], acc[mi][ni][3]));
        }
    }
}

// =====================================================================
// GEMM2: out += w * (h Wdown); fp16 cp.async + ldmatrix pipeline
// BM=128, BN=128, BK=32, 8 warps, warp tile 32x64
// =====================================================================
__global__ __launch_bounds__(256, 2)
void gemm2_mma(float* __restrict__ out) {
    extern __shared__ __half sh[];
    int z = blockIdx.z, col0 = blockIdx.x * 128, row0 = blockIdx.y * 128;

    int cnt, e, K; const __half *Ap, *Bp;
    if (z == 0) {
        e = -1; cnt = T_; K = IS_;
        Ap = g_hs;
        Bp = g_wsdT + (size_t)col0 * IS_;
    } else {
        e = z - 1; cnt = g_counts[e]; K = I_;
        if (row0 >= cnt) return;
        Ap = g_h + (size_t)e * T_ * I_;
        Bp = g_wdT + ((size_t)e * H_ + col0) * I_;
    }
    if (row0 >= cnt) return;

    uint32_t smb = smem_u32(sh);
    int tid = threadIdx.x;
    uint32_t dst_off;
    const __half* src;
    if (tid < 128) {
        int r = row0 + tid;
        if (r >= cnt) r = row0;          // clamp; result discarded
        dst_off = (uint32_t)tid * (SAH * 2);
        src = Ap + (size_t)r * K;
    } else {
        int n = tid - 128;
        dst_off = (uint32_t)(A_H + n * SAH) * 2;
        src = Bp + (size_t)n * K;
    }

    int lane = tid & 31, wid = tid >> 5, gid = lane >> 2, t4 = lane & 3;
    int wm = wid & 3, wn = wid >> 2;

    uint32_t aOff = ((uint32_t)(wm * 32 + (lane & 15)) * SAH + (uint32_t)(lane >> 4) * 8) * 2;
    uint32_t bOff = ((uint32_t)A_H +
                     (uint32_t)(wn * 64 + (lane & 7) + ((lane >> 4) & 1) * 8) * SAH +
                     (uint32_t)((lane >> 3) & 1) * 8) * 2;

    float acc[2][8][4] = {};

    const int NIT = K / 32;
    #pragma unroll 1
    for (int p = 0; p < 3; p++) {
        uint32_t d = smb + (uint32_t)p * STAGE_B + dst_off;
        const __half* s = src + p * 32;
        CP16(d, s); CP16(d + 16, s + 8); CP16(d + 32, s + 16); CP16(d + 48, s + 24);
        CP_COMMIT();
    }
    for (int it = 0; it < NIT; ++it) {
        if (it < NIT - 3) CP_WAIT(2); else CP_WAIT(0);
        __syncthreads();
        if (it + 3 < NIT) {
            uint32_t d = smb + (uint32_t)((it + 3) & (NSTG - 1)) * STAGE_B + dst_off;
            const __half* s = src + (it + 3) * 32;
            CP16(d, s); CP16(d + 16, s + 8); CP16(d + 32, s + 16); CP16(d + 48, s + 24);
            CP_COMMIT();
        }
        uint32_t sbase = smb + (uint32_t)(it & (NSTG - 1)) * STAGE_B;
        #pragma unroll
        for (int kb = 0; kb < 32; kb += 16) {
            uint32_t af[2][4], bf[8][2];
            #pragma unroll
            for (int mi = 0; mi < 2; mi++)
                LDSM4(af[mi][0], af[mi][1], af[mi][2], af[mi][3],
                      sbase + aOff + (uint32_t)(mi * 16 * SAH + kb) * 2);
            #pragma unroll
            for (int nj = 0; nj < 4; nj++)
                LDSM4(bf[2 * nj][0], bf[2 * nj][1], bf[2 * nj + 1][0], bf[2 * nj + 1][1],
                      sbase + bOff + (uint32_t)(nj * 16 * SAH + kb) * 2);
            #pragma unroll
            for (int mi = 0; mi < 2; mi++)
                #pragma unroll
                for (int ni = 0; ni < 8; ni++)
                    mma16(acc[mi][ni], af[mi], bf[ni]);
        }
    }

    // epilogue: weighted atomic accumulate
    #pragma unroll
    for (int mi = 0; mi < 2; mi++) {
        int rb = row0 + wm * 32 + mi * 16 + gid;
        #pragma unroll
        for (int h = 0; h < 2; h++) {
            int r = rb + h * 8;
            if (r < cnt) {
                int   t = (z == 0) ? r : g_tok[e * T_ + r];
                float w = (z == 0) ? 1.f : g_wt[e * T_ + r];
                float* op = out + (size_t)t * H_ + col0 + wn * 64;
                #pragma unroll
                for (int ni = 0; ni < 8; ni++) {
                    int c = ni * 8 + t4 * 2;
                    atomicAdd(op + c,     w * acc[mi][ni][h * 2 + 0]);
                    atomicAdd(op + c + 1, w * acc[mi][ni][h * 2 + 1]);
                }
            }
        }
    }
}

// ---------------- launch ----------------
extern "C" void kernel_launch(void* const* d_in, const int* in_sizes, int n_in,
                              void* d_out, int out_size) {
    const float* x   = (const float*)d_in[0];
    const float* rw  = (const float*)d_in[1];
    const float* wg  = (const float*)d_in[2];
    const float* wu  = (const float*)d_in[3];
    const float* wd  = (const float*)d_in[4];
    const float* wgu = (const float*)d_in[5];
    const float* wsd = (const float*)d_in[6];

    cudaFuncSetAttribute(gemm1_mma, cudaFuncAttributeMaxDynamicSharedMemorySize, GEMM_SMEM);
    cudaFuncSetAttribute(gemm2_mma, cudaFuncAttributeMaxDynamicSharedMemorySize, GEMM_SMEM);

    cudaMemsetAsync(d_out, 0, (size_t)out_size * sizeof(float), 0);
    zero_counts_kernel<<<1, 32>>>();
    router_kernel<<<T_, 256>>>(x, rw);
    prepass_kernel<<<PRE_BLKS, 256>>>(x, wg, wu, wd, wgu, wsd);

    // z=0 = shared expert (largest K) scheduled first
    gemm1_mma<<<dim3(IS_ / 64, T_ / 128, E_ + 1), 256, GEMM_SMEM>>>();
    gemm2_mma<<<dim3(H_ / 128, T_ / 128, E_ + 1), 256, GEMM_SMEM>>>((float*)d_out);
}